// round 15
// baseline (speedup 1.0000x reference)
#include <cuda_runtime.h>
#include <cstdint>

#define B_ 2048
#define S_ 64
#define D_ 512
#define N_ 64
#define A_ 64
#define F_ 512

typedef unsigned long long u64;

// ---------------- persistent device scratch ------------------------------------
__device__ __align__(16) float g_k[N_ * F_];
__device__ __align__(16) float g_kqP[(size_t)D_ * N_];     // plain [d][n], scale folded
__device__ __align__(16) float g_M1e[68 * F_];
__device__ __align__(16) float g_G2[A_ * A_];
__device__ __align__(16) float g_wb[A_];
__device__ __align__(16) float g_wsum[A_];
__device__ __align__(16) float g_scal[2];
__device__ __align__(16) float g_QeT[(size_t)B_ * 68 * 128];  // dup pairs [b][k][2s]

// ---------------- f32x2 helpers --------------------------------------------------
__device__ __forceinline__ u64 fma2(u64 a, u64 b, u64 c) {
    u64 d;
    asm("fma.rn.f32x2 %0, %1, %2, %3;" : "=l"(d) : "l"(a), "l"(b), "l"(c));
    return d;
}
__device__ __forceinline__ u64 dup2(float v) {
    u64 d;
    asm("mov.b64 %0, {%1, %1};" : "=l"(d) : "f"(v));
    return d;
}
__device__ __forceinline__ u64 pk2(float a, float b) {
    u64 d;
    asm("mov.b64 %0, {%1, %2};" : "=l"(d) : "f"(a), "f"(b));
    return d;
}
__device__ __forceinline__ float2 unpk(u64 v) {
    float2 r;
    asm("mov.b64 {%0, %1}, %2;" : "=f"(r.x), "=f"(r.y) : "l"(v));
    return r;
}

// ---------------- setup: M1e, G2, scalars, k -------------------------------------
__global__ __launch_bounds__(512)
void setup_master(const float* __restrict__ W_ae, const float* __restrict__ b_ae,
                  const float* __restrict__ W_ie, const float* __restrict__ b_ie,
                  const float* __restrict__ ln_g, const float* __restrict__ ln_b,
                  const float* __restrict__ Wk, const float* __restrict__ Wv) {
    const int t = threadIdx.x;
    const int b = blockIdx.x;
    if (b < 64) {
        float a0 = 0.f, a1 = 0.f, a2 = 0.f, a3 = 0.f;
        for (int f = 0; f < F_; f += 4) {
            float4 wv = *(const float4*)&Wv[t * 512 + f];
            float4 lg = *(const float4*)&ln_g[f];
            a0 += W_ae[(f + 0) * A_ + b] * lg.x * wv.x;
            a1 += W_ae[(f + 1) * A_ + b] * lg.y * wv.y;
            a2 += W_ae[(f + 2) * A_ + b] * lg.z * wv.z;
            a3 += W_ae[(f + 3) * A_ + b] * lg.w * wv.w;
        }
        g_M1e[b * 512 + t] = (a0 + a1) + (a2 + a3);
    } else if (b == 64) {
        float c1 = 0.f, c2 = 0.f, c3 = 0.f;
        for (int f = 0; f < F_; f += 2) {
            float2 wv = *(const float2*)&Wv[t * 512 + f];
            c1 += b_ae[f] * ln_g[f] * wv.x + b_ae[f + 1] * ln_g[f + 1] * wv.y;
            c2 += ln_g[f] * wv.x + ln_g[f + 1] * wv.y;
            c3 += ln_b[f] * wv.x + ln_b[f + 1] * wv.y;
        }
        g_M1e[64 * 512 + t] = c1;
        g_M1e[65 * 512 + t] = c2;
        g_M1e[66 * 512 + t] = c3;
        g_M1e[67 * 512 + t] = 0.f;
    } else if (b < 73) {
        int idx = (b - 65) * 512 + t;
        int al = idx & 63, be = idx >> 6;
        float a0 = 0.f, a1 = 0.f, a2 = 0.f, a3 = 0.f;
#pragma unroll 4
        for (int f = 0; f < F_; f += 4) {
            a0 += W_ae[(f + 0) * A_ + al] * W_ae[(f + 0) * A_ + be];
            a1 += W_ae[(f + 1) * A_ + al] * W_ae[(f + 1) * A_ + be];
            a2 += W_ae[(f + 2) * A_ + al] * W_ae[(f + 2) * A_ + be];
            a3 += W_ae[(f + 3) * A_ + al] * W_ae[(f + 3) * A_ + be];
        }
        g_G2[al * A_ + be] = (a0 + a1) + (a2 + a3);
    } else if (b == 73) {
        if (t < 64) {
            float aw = 0.f, as = 0.f;
#pragma unroll 4
            for (int f = 0; f < F_; f++) {
                float w = W_ae[f * A_ + t];
                aw += w * b_ae[f];
                as += w;
            }
            g_wb[t] = aw;
            g_wsum[t] = as;
        } else if (t == 64) {
            float bb = 0.f, sb = 0.f;
            for (int f = 0; f < F_; f++) {
                float v = b_ae[f];
                bb += v * v;
                sb += v;
            }
            g_scal[0] = bb;
            g_scal[1] = sb;
        }
    } else {
        int idx = (b - 74) * 512 + t;
        int n = idx & 63;
        int g = idx >> 6;
        float a0 = 0.f, a1 = 0.f, a2 = 0.f, a3 = 0.f;
#pragma unroll 4
        for (int f = 0; f < F_; f += 4) {
            a0 += (W_ie[(f + 0) * N_ + n] + b_ie[f + 0]) * Wk[g * F_ + f + 0];
            a1 += (W_ie[(f + 1) * N_ + n] + b_ie[f + 1]) * Wk[g * F_ + f + 1];
            a2 += (W_ie[(f + 2) * N_ + n] + b_ie[f + 2]) * Wk[g * F_ + f + 2];
            a3 += (W_ie[(f + 3) * N_ + n] + b_ie[f + 3]) * Wk[g * F_ + f + 3];
        }
        g_k[n * F_ + g] = (a0 + a1) + (a2 + a3);
    }
}

// ---------------- setup 2: kqP plain; split so attnq is 4th launch ---------------
__global__ void setup_kq(const float* __restrict__ Wq, int y0) {
    int d = (blockIdx.y + y0 * 4) * 64 + threadIdx.x;
    int n0 = blockIdx.x * 8;
    float acc[8];
#pragma unroll
    for (int j = 0; j < 8; j++) acc[j] = 0.f;
#pragma unroll 4
    for (int f = 0; f < F_; f++) {
        float wq = Wq[f * D_ + d];
#pragma unroll
        for (int j = 0; j < 8; j++)
            acc[j] += g_k[(n0 + j) * F_ + f] * wq;
    }
    const float scale = 0.04419417382415922f;  // 512^-0.5
#pragma unroll
    for (int j = 0; j < 8; j++)
        g_kqP[(size_t)d * 64 + n0 + j] = acc[j] * scale;
}

// =================== kernel A v6: broadcast-economy phase L =======================
// 128 threads: warp w: nh = w>>1 (n half), sh = w&1 (s half); lane l -> n = nh*32+l.
// Thread owns 1 n x 32 s. All inner-loop loads are 1-wavefront class:
//   kq: lane-contiguous LDS.32; slots: warp-uniform broadcast LDS.128.
// smem: R1 [0,4356): sSlT 64x64 swizzled -> sActR 67x65 (4355)
//       R2 [4356,8708): sKq 64x64 plain -> sAttn 64x68 (4352)
//       RED [8708,8836): sRed 128 -> sMu 64 + sRs 64
#define AQ_R1     0
#define AQ_R2     4356
#define AQ_RED    (4356 + 4352)
#define AQ_FLOATS (AQ_RED + 128)
__global__ __launch_bounds__(128, 5)
void attnq_kernel(const float* __restrict__ slots,
                  const float* __restrict__ actions,
                  float* __restrict__ out_attn) {
    extern __shared__ float sq[];
    float* sSlT  = sq + AQ_R1;     // [d][64] XOR-16B swizzled
    float* sActR = sq + AQ_R1;     // [k][65] after phase L
    float* sKq   = sq + AQ_R2;     // [d][64] plain
    float* sAttn = sq + AQ_R2;     // [n][68] after phase L
    float* sRed  = sq + AQ_RED;    // 128 (softmax exchange)
    float* sMu   = sq + AQ_RED;    // 64 (stats, after softmax)
    float* sRs   = sMu + 64;       // 64

    const int t = threadIdx.x;
    const int b = blockIdx.x;
    const float* slots_b = slots + (size_t)b * S_ * D_;
    const float* act_b   = actions + (size_t)b * N_ * A_;
    const int w = t >> 5, l = t & 31;
    const int nh = w >> 1, sh = w & 1;
    const int n = nh * 32 + l;      // this thread's n row

    // ======== Phase L: acc[16 u64] = logits[n][s-pairs], s = sh*32..sh*32+31 ====
    u64 acc[16];
#pragma unroll
    for (int j = 0; j < 16; j++) acc[j] = 0ull;

    for (int dc = 0; dc < 8; dc++) {
        if (dc) __syncthreads();
        // stage kq chunk plain [64 d][64 n]: dense LDG.128 -> dense STS.128
#pragma unroll
        for (int j = 0; j < 8; j++) {
            int idx = t + j * 128;
            int d = idx >> 4, n4 = idx & 15;
            float4 v = *(const float4*)&g_kqP[(size_t)(dc * 64 + d) * 64 + n4 * 4];
            *(float4*)&sKq[d * 64 + n4 * 4] = v;
        }
        // stage slots transposed [d][s], XOR-16B swizzle: chunk c=s>>2 -> c^(d&15)
#pragma unroll
        for (int j = 0; j < 8; j++) {
            int idx = t + j * 128;
            int s = idx >> 4, q = idx & 15;
            float4 v = *(const float4*)&slots_b[s * 512 + dc * 64 + q * 4];
            int c = s >> 2, slo = s & 3;
            float vv[4] = {v.x, v.y, v.z, v.w};
#pragma unroll
            for (int k = 0; k < 4; k++) {
                int d = q * 4 + k;
                sSlT[d * 64 + ((c ^ (d & 15)) << 2) + slo] = vv[k];
            }
        }
        __syncthreads();

#pragma unroll 4
        for (int d = 0; d < 64; d++) {
            u64 kd = dup2(sKq[d * 64 + nh * 32 + l]);   // lane-contig, 1 wf
            int dx = d & 15;
            const float* row = &sSlT[d * 64];
#pragma unroll
            for (int cc = 0; cc < 8; cc += 2) {
                int c0 = sh * 8 + cc;
                ulonglong2 v0 = *(const ulonglong2*)&row[((c0 ^ dx) << 2)];
                ulonglong2 v1 = *(const ulonglong2*)&row[(((c0 + 1) ^ dx) << 2)];
                acc[2 * cc + 0] = fma2(kd, v0.x, acc[2 * cc + 0]);
                acc[2 * cc + 1] = fma2(kd, v0.y, acc[2 * cc + 1]);
                acc[2 * cc + 2] = fma2(kd, v1.x, acc[2 * cc + 2]);
                acc[2 * cc + 3] = fma2(kd, v1.y, acc[2 * cc + 3]);
            }
        }
    }
    __syncthreads();   // phase L done; R1/R2 repurposed

    // ======== softmax over s (32 in-register + cross-warp 2-float exchange) =====
    {
        float lv[32];
#pragma unroll
        for (int j = 0; j < 16; j++) {
            float2 p = unpk(acc[j]);
            lv[2 * j] = p.x;
            lv[2 * j + 1] = p.y;
        }
        float pm = lv[0];
#pragma unroll
        for (int j = 1; j < 32; j++) pm = fmaxf(pm, lv[j]);
        sRed[sh * 64 + n] = pm;
        __syncthreads();
        float M = fmaxf(sRed[n], sRed[64 + n]);
        float ps = 0.f;
#pragma unroll
        for (int j = 0; j < 32; j++) {
            lv[j] = __expf(lv[j] - M);
            ps += lv[j];
        }
        __syncthreads();          // all M reads done before overwrite
        sRed[sh * 64 + n] = ps;
        __syncthreads();
        float inv = 1.f / (sRed[n] + sRed[64 + n]);
#pragma unroll
        for (int j = 0; j < 16; j++) {
            float e0 = lv[2 * j] * inv, e1 = lv[2 * j + 1] * inv;
            *(u64*)&sAttn[n * 68 + sh * 32 + 2 * j] = pk2(e0, e1);
        }
    }
    __syncthreads();

    // ======== write out_attn coalesced from sAttn ========
    {
        float* o2 = out_attn + (size_t)b * N_ * S_;
#pragma unroll
        for (int j = 0; j < 8; j++) {
            int i4 = t + j * 128;
            int nn = i4 >> 4, sqd = i4 & 15;
            *(float4*)&o2[nn * 64 + sqd * 4] =
                *(const float4*)&sAttn[nn * 68 + sqd * 4];
        }
    }
    __syncthreads();

    // ======== LN stats: n = t>>1, seg = t&1; actions via __ldg ========
    {
        const int nn = t >> 1, seg = t & 1;
        const float* an = act_b + nn * 64;
        float dotj[32];
#pragma unroll
        for (int j = 0; j < 32; j++) dotj[j] = 0.f;
        for (int al = 0; al < 64; al++) {
            float av = __ldg(&an[al]);
            const float4* g4 = (const float4*)&g_G2[al * 64 + seg * 32];
#pragma unroll
            for (int q = 0; q < 8; q++) {
                float4 g = g4[q];
                dotj[q * 4 + 0] += av * g.x;
                dotj[q * 4 + 1] += av * g.y;
                dotj[q * 4 + 2] += av * g.z;
                dotj[q * 4 + 3] += av * g.w;
            }
        }
        float quad = 0.f, wbp = 0.f, wsp = 0.f;
#pragma unroll
        for (int j = 0; j < 32; j++) {
            int be = seg * 32 + j;
            float ab = __ldg(&an[be]);
            quad += ab * dotj[j];
            wbp += ab * g_wb[be];
            wsp += ab * g_wsum[be];
        }
        quad += __shfl_xor_sync(0xffffffffu, quad, 1);
        wbp  += __shfl_xor_sync(0xffffffffu, wbp, 1);
        wsp  += __shfl_xor_sync(0xffffffffu, wsp, 1);
        if (seg == 0) {
            float bb = g_scal[0], sb = g_scal[1];
            float mu = (wsp + sb) * (1.f / 512.f);
            float e2 = (quad + 2.f * wbp + bb) * (1.f / 512.f);
            float var = e2 - mu * mu;
            sMu[nn] = mu;
            sRs[nn] = rsqrtf(var + 1e-5f);
        }
    }
    __syncthreads();

    // ======== actRaug -> sActR [k][65] (actions via __ldg) ========
    {
        const int nn = t >> 1, half = t & 1;
        const float* an = act_b + nn * 64;
        float rs = sRs[nn];
#pragma unroll
        for (int i = 0; i < 32; i++) {
            int al = half * 32 + i;
            sActR[al * 65 + nn] = rs * __ldg(&an[al]);
        }
        if (half == 0) {
            sActR[64 * 65 + nn] = rs;
            sActR[65 * 65 + nn] = -rs * sMu[nn];
            sActR[66 * 65 + nn] = 1.f;
        }
    }
    __syncthreads();

    // ======== Qe: QeT[k][s] = sum_n attn[n][s]*actR[n][k] + eps*colsum ========
    float* qdst_base = g_QeT + (size_t)b * 8704;
#pragma unroll
    for (int pass = 0; pass < 2; pass++) {
        int k = pass ? (64 + (t >> 1)) : (t >> 1);
        bool active = (pass == 0) || (t < 6);
        if (active) {
            const int shalf = t & 1;
            u64 qacc[16];
#pragma unroll
            for (int j = 0; j < 16; j++) qacc[j] = 0ull;
            float cs = 0.f;
            for (int nn = 0; nn < 64; nn++) {
                float a = sActR[k * 65 + nn];
                cs += a;
                u64 ad = dup2(a);
                const ulonglong2* ep =
                    (const ulonglong2*)&sAttn[nn * 68 + shalf * 32];
#pragma unroll
                for (int jj = 0; jj < 8; jj++) {
                    ulonglong2 e = ep[jj];
                    qacc[2 * jj]     = fma2(ad, e.x, qacc[2 * jj]);
                    qacc[2 * jj + 1] = fma2(ad, e.y, qacc[2 * jj + 1]);
                }
            }
            u64 ec = dup2(cs * 1e-8f);
            u64 one = dup2(1.f);
            float* dst = qdst_base + k * 128 + shalf * 64;
#pragma unroll
            for (int j = 0; j < 16; j++) {
                qacc[j] = fma2(ec, one, qacc[j]);
                float2 p = unpk(qacc[j]);
                *(float4*)(dst + 4 * j) = make_float4(p.x, p.x, p.y, p.y);
            }
        }
    }
}

// =================== kernel B: out = Qe @ M1e (R10/R14-measured version) =========
__global__ __launch_bounds__(256, 2)
void out_kernel(float* __restrict__ out_slots) {
    const int t = threadIdx.x;
    const int b = blockIdx.x;
    const int fy = blockIdx.y;
    const int w = t >> 5, l = t & 31;
    const int s0 = w * 8;
    const int f = fy * 256 + l * 8;
    const float* Qb = g_QeT + (size_t)b * 8704;

    u64 acc[8][4];
#pragma unroll
    for (int i = 0; i < 8; i++)
#pragma unroll
        for (int p = 0; p < 4; p++) acc[i][p] = 0ull;

#pragma unroll 4
    for (int k = 0; k < 67; k++) {
        const ulonglong2* m = (const ulonglong2*)&g_M1e[k * 512 + f];
        ulonglong2 m0 = m[0], m1 = m[1];
        const ulonglong2* q = (const ulonglong2*)&Qb[k * 128 + 2 * s0];
        ulonglong2 q0 = q[0], q1 = q[1], q2 = q[2], q3 = q[3];
        u64 e[8] = {q0.x, q0.y, q1.x, q1.y, q2.x, q2.y, q3.x, q3.y};
#pragma unroll
        for (int i = 0; i < 8; i++) {
            acc[i][0] = fma2(e[i], m0.x, acc[i][0]);
            acc[i][1] = fma2(e[i], m0.y, acc[i][1]);
            acc[i][2] = fma2(e[i], m1.x, acc[i][2]);
            acc[i][3] = fma2(e[i], m1.y, acc[i][3]);
        }
    }

    float* o1 = out_slots + (size_t)b * S_ * F_ + f;
#pragma unroll
    for (int i = 0; i < 8; i++) {
        float2 p0 = unpk(acc[i][0]), p1 = unpk(acc[i][1]);
        float2 p2 = unpk(acc[i][2]), p3 = unpk(acc[i][3]);
        float* dst = o1 + (s0 + i) * 512;
        *(float4*)dst       = make_float4(p0.x, p0.y, p1.x, p1.y);
        *(float4*)(dst + 4) = make_float4(p2.x, p2.y, p3.x, p3.y);
    }
}

// ---------------- launch ----------------------------------------------------------
extern "C" void kernel_launch(void* const* d_in, const int* in_sizes, int n_in,
                              void* d_out, int out_size) {
    const float* slots   = (const float*)d_in[0];
    const float* actions = (const float*)d_in[1];
    const float* W_ae    = (const float*)d_in[2];
    const float* b_ae    = (const float*)d_in[3];
    const float* W_ie    = (const float*)d_in[4];
    const float* b_ie    = (const float*)d_in[5];
    const float* ln_g    = (const float*)d_in[6];
    const float* ln_b    = (const float*)d_in[7];
    const float* Wq      = (const float*)d_in[8];
    const float* Wk      = (const float*)d_in[9];
    const float* Wv      = (const float*)d_in[10];

    float* out      = (float*)d_out;
    float* out_attn = out + (size_t)B_ * S_ * F_;

    setup_master<<<138, 512>>>(W_ae, b_ae, W_ie, b_ie, ln_g, ln_b, Wk, Wv);
    setup_kq<<<dim3(8, 4), 64>>>(Wq, 0);     // launch 2
    setup_kq<<<dim3(8, 4), 64>>>(Wq, 1);     // launch 3

    const size_t AQ_BYTES = AQ_FLOATS * sizeof(float);
    cudaFuncSetAttribute(attnq_kernel,
                         cudaFuncAttributeMaxDynamicSharedMemorySize, (int)AQ_BYTES);
    attnq_kernel<<<B_, 128, AQ_BYTES>>>(slots, actions, out_attn);  // launch 4 -> profiled

    out_kernel<<<dim3(B_, 2), 256>>>(out);
}

// round 16
// speedup vs baseline: 1.1503x; 1.1503x over previous
#include <cuda_runtime.h>
#include <cstdint>

#define B_ 2048
#define S_ 64
#define D_ 512
#define N_ 64
#define A_ 64
#define F_ 512

typedef unsigned long long u64;

// ---------------- persistent device scratch ------------------------------------
__device__ __align__(16) float g_k[N_ * F_];
__device__ __align__(16) float g_kqP[(size_t)D_ * N_];     // plain [d][n], scale folded
__device__ __align__(16) float g_M1e[68 * F_];
__device__ __align__(16) float g_G2[A_ * A_];
__device__ __align__(16) float g_wb[A_];
__device__ __align__(16) float g_wsum[A_];
__device__ __align__(16) float g_scal[2];
__device__ __align__(16) float g_QeT[(size_t)B_ * 68 * 128];  // dup pairs [b][k][2s]

// ---------------- f32x2 / async helpers -------------------------------------------
__device__ __forceinline__ u64 fma2(u64 a, u64 b, u64 c) {
    u64 d;
    asm("fma.rn.f32x2 %0, %1, %2, %3;" : "=l"(d) : "l"(a), "l"(b), "l"(c));
    return d;
}
__device__ __forceinline__ u64 dup2(float v) {
    u64 d;
    asm("mov.b64 %0, {%1, %1};" : "=l"(d) : "f"(v));
    return d;
}
__device__ __forceinline__ u64 pk2(float a, float b) {
    u64 d;
    asm("mov.b64 %0, {%1, %2};" : "=l"(d) : "f"(a), "f"(b));
    return d;
}
__device__ __forceinline__ float2 unpk(u64 v) {
    float2 r;
    asm("mov.b64 {%0, %1}, %2;" : "=f"(r.x), "=f"(r.y) : "l"(v));
    return r;
}
__device__ __forceinline__ uint32_t smem_u32(const void* p) {
    uint32_t a;
    asm("{ .reg .u64 t; cvta.to.shared.u64 t, %1; cvt.u32.u64 %0, t; }"
        : "=r"(a) : "l"(p));
    return a;
}
__device__ __forceinline__ void cp16(uint32_t dst, const void* src) {
    asm volatile("cp.async.ca.shared.global [%0], [%1], 16;"
                 :: "r"(dst), "l"(src) : "memory");
}
#define CP_COMMIT() asm volatile("cp.async.commit_group;" ::: "memory")
#define CP_WAIT0()  asm volatile("cp.async.wait_group 0;" ::: "memory")

// ---------------- setup: M1e, G2, scalars, k -------------------------------------
__global__ __launch_bounds__(512)
void setup_master(const float* __restrict__ W_ae, const float* __restrict__ b_ae,
                  const float* __restrict__ W_ie, const float* __restrict__ b_ie,
                  const float* __restrict__ ln_g, const float* __restrict__ ln_b,
                  const float* __restrict__ Wk, const float* __restrict__ Wv) {
    const int t = threadIdx.x;
    const int b = blockIdx.x;
    if (b < 64) {
        float a0 = 0.f, a1 = 0.f, a2 = 0.f, a3 = 0.f;
        for (int f = 0; f < F_; f += 4) {
            float4 wv = *(const float4*)&Wv[t * 512 + f];
            float4 lg = *(const float4*)&ln_g[f];
            a0 += W_ae[(f + 0) * A_ + b] * lg.x * wv.x;
            a1 += W_ae[(f + 1) * A_ + b] * lg.y * wv.y;
            a2 += W_ae[(f + 2) * A_ + b] * lg.z * wv.z;
            a3 += W_ae[(f + 3) * A_ + b] * lg.w * wv.w;
        }
        g_M1e[b * 512 + t] = (a0 + a1) + (a2 + a3);
    } else if (b == 64) {
        float c1 = 0.f, c2 = 0.f, c3 = 0.f;
        for (int f = 0; f < F_; f += 2) {
            float2 wv = *(const float2*)&Wv[t * 512 + f];
            c1 += b_ae[f] * ln_g[f] * wv.x + b_ae[f + 1] * ln_g[f + 1] * wv.y;
            c2 += ln_g[f] * wv.x + ln_g[f + 1] * wv.y;
            c3 += ln_b[f] * wv.x + ln_b[f + 1] * wv.y;
        }
        g_M1e[64 * 512 + t] = c1;
        g_M1e[65 * 512 + t] = c2;
        g_M1e[66 * 512 + t] = c3;
        g_M1e[67 * 512 + t] = 0.f;
    } else if (b < 73) {
        int idx = (b - 65) * 512 + t;
        int al = idx & 63, be = idx >> 6;
        float a0 = 0.f, a1 = 0.f, a2 = 0.f, a3 = 0.f;
#pragma unroll 4
        for (int f = 0; f < F_; f += 4) {
            a0 += W_ae[(f + 0) * A_ + al] * W_ae[(f + 0) * A_ + be];
            a1 += W_ae[(f + 1) * A_ + al] * W_ae[(f + 1) * A_ + be];
            a2 += W_ae[(f + 2) * A_ + al] * W_ae[(f + 2) * A_ + be];
            a3 += W_ae[(f + 3) * A_ + al] * W_ae[(f + 3) * A_ + be];
        }
        g_G2[al * A_ + be] = (a0 + a1) + (a2 + a3);
    } else if (b == 73) {
        if (t < 64) {
            float aw = 0.f, as = 0.f;
#pragma unroll 4
            for (int f = 0; f < F_; f++) {
                float w = W_ae[f * A_ + t];
                aw += w * b_ae[f];
                as += w;
            }
            g_wb[t] = aw;
            g_wsum[t] = as;
        } else if (t == 64) {
            float bb = 0.f, sb = 0.f;
            for (int f = 0; f < F_; f++) {
                float v = b_ae[f];
                bb += v * v;
                sb += v;
            }
            g_scal[0] = bb;
            g_scal[1] = sb;
        }
    } else {
        int idx = (b - 74) * 512 + t;
        int n = idx & 63;
        int g = idx >> 6;
        float a0 = 0.f, a1 = 0.f, a2 = 0.f, a3 = 0.f;
#pragma unroll 4
        for (int f = 0; f < F_; f += 4) {
            a0 += (W_ie[(f + 0) * N_ + n] + b_ie[f + 0]) * Wk[g * F_ + f + 0];
            a1 += (W_ie[(f + 1) * N_ + n] + b_ie[f + 1]) * Wk[g * F_ + f + 1];
            a2 += (W_ie[(f + 2) * N_ + n] + b_ie[f + 2]) * Wk[g * F_ + f + 2];
            a3 += (W_ie[(f + 3) * N_ + n] + b_ie[f + 3]) * Wk[g * F_ + f + 3];
        }
        g_k[n * F_ + g] = (a0 + a1) + (a2 + a3);
    }
}

// ---------------- setup 2: kqP plain (single launch, grid 8x8) --------------------
__global__ void setup_kq(const float* __restrict__ Wq) {
    int d = blockIdx.y * 64 + threadIdx.x;
    int n0 = blockIdx.x * 8;
    float acc[8];
#pragma unroll
    for (int j = 0; j < 8; j++) acc[j] = 0.f;
#pragma unroll 4
    for (int f = 0; f < F_; f++) {
        float wq = Wq[f * D_ + d];
#pragma unroll
        for (int j = 0; j < 8; j++)
            acc[j] += g_k[(n0 + j) * F_ + f] * wq;
    }
    const float scale = 0.04419417382415922f;  // 512^-0.5
#pragma unroll
    for (int j = 0; j < 8; j++)
        g_kqP[(size_t)d * 64 + n0 + j] = acc[j] * scale;
}

// =================== kernel A v6.1: broadcast-economy + cp.async kq ===============
#define AQ_R1     0
#define AQ_R2     4356
#define AQ_RED    (4356 + 4352)
#define AQ_FLOATS (AQ_RED + 128)
__global__ __launch_bounds__(128, 5)
void attnq_kernel(const float* __restrict__ slots,
                  const float* __restrict__ actions,
                  float* __restrict__ out_attn) {
    extern __shared__ float sq[];
    float* sSlT  = sq + AQ_R1;     // [d][64] XOR-16B swizzled
    float* sActR = sq + AQ_R1;     // [k][65] after phase L
    float* sKq   = sq + AQ_R2;     // [d][64] plain
    float* sAttn = sq + AQ_R2;     // [n][68] after phase L
    float* sRed  = sq + AQ_RED;    // 128 (softmax exchange)
    float* sMu   = sq + AQ_RED;    // 64 (stats, after softmax)
    float* sRs   = sMu + 64;       // 64

    const int t = threadIdx.x;
    const int b = blockIdx.x;
    const float* slots_b = slots + (size_t)b * S_ * D_;
    const float* act_b   = actions + (size_t)b * N_ * A_;
    const int w = t >> 5, l = t & 31;
    const int nh = w >> 1, sh = w & 1;
    const int n = nh * 32 + l;
    const uint32_t sKqAddr = smem_u32(sKq);

    // ======== Phase L ========
    u64 acc[16];
#pragma unroll
    for (int j = 0; j < 16; j++) acc[j] = 0ull;

    for (int dc = 0; dc < 8; dc++) {
        if (dc) __syncthreads();
        // kq chunk via cp.async (pure dense 16B copies; overlaps with slot staging)
#pragma unroll
        for (int j = 0; j < 8; j++) {
            int idx = t + j * 128;            // 1024 16B units
            cp16(sKqAddr + idx * 16, &g_kqP[(size_t)dc * 4096 + idx * 4]);
        }
        CP_COMMIT();
        // slots transposed [d][s] with XOR-16B swizzle
#pragma unroll
        for (int j = 0; j < 8; j++) {
            int idx = t + j * 128;
            int s = idx >> 4, q = idx & 15;
            float4 v = *(const float4*)&slots_b[s * 512 + dc * 64 + q * 4];
            int c = s >> 2, slo = s & 3;
            float vv[4] = {v.x, v.y, v.z, v.w};
#pragma unroll
            for (int k = 0; k < 4; k++) {
                int d = q * 4 + k;
                sSlT[d * 64 + ((c ^ (d & 15)) << 2) + slo] = vv[k];
            }
        }
        CP_WAIT0();
        __syncthreads();

#pragma unroll 4
        for (int d = 0; d < 64; d++) {
            u64 kd = dup2(sKq[d * 64 + nh * 32 + l]);   // lane-contig, 1 wf
            int dx = d & 15;
            const float* row = &sSlT[d * 64];
#pragma unroll
            for (int cc = 0; cc < 8; cc += 2) {
                int c0 = sh * 8 + cc;
                ulonglong2 v0 = *(const ulonglong2*)&row[((c0 ^ dx) << 2)];
                ulonglong2 v1 = *(const ulonglong2*)&row[(((c0 + 1) ^ dx) << 2)];
                acc[2 * cc + 0] = fma2(kd, v0.x, acc[2 * cc + 0]);
                acc[2 * cc + 1] = fma2(kd, v0.y, acc[2 * cc + 1]);
                acc[2 * cc + 2] = fma2(kd, v1.x, acc[2 * cc + 2]);
                acc[2 * cc + 3] = fma2(kd, v1.y, acc[2 * cc + 3]);
            }
        }
    }
    __syncthreads();

    // ======== softmax over s ========
    {
        float lv[32];
#pragma unroll
        for (int j = 0; j < 16; j++) {
            float2 p = unpk(acc[j]);
            lv[2 * j] = p.x;
            lv[2 * j + 1] = p.y;
        }
        float pm = lv[0];
#pragma unroll
        for (int j = 1; j < 32; j++) pm = fmaxf(pm, lv[j]);
        sRed[sh * 64 + n] = pm;
        __syncthreads();
        float M = fmaxf(sRed[n], sRed[64 + n]);
        float ps = 0.f;
#pragma unroll
        for (int j = 0; j < 32; j++) {
            lv[j] = __expf(lv[j] - M);
            ps += lv[j];
        }
        __syncthreads();
        sRed[sh * 64 + n] = ps;
        __syncthreads();
        float inv = 1.f / (sRed[n] + sRed[64 + n]);
#pragma unroll
        for (int j = 0; j < 16; j++) {
            float e0 = lv[2 * j] * inv, e1 = lv[2 * j + 1] * inv;
            *(u64*)&sAttn[n * 68 + sh * 32 + 2 * j] = pk2(e0, e1);
        }
    }
    __syncthreads();

    // ======== write out_attn coalesced ========
    {
        float* o2 = out_attn + (size_t)b * N_ * S_;
#pragma unroll
        for (int j = 0; j < 8; j++) {
            int i4 = t + j * 128;
            int nn = i4 >> 4, sqd = i4 & 15;
            *(float4*)&o2[nn * 64 + sqd * 4] =
                *(const float4*)&sAttn[nn * 68 + sqd * 4];
        }
    }
    __syncthreads();

    // ======== LN stats: n = t>>1, seg = t&1; actions via __ldg ========
    {
        const int nn = t >> 1, seg = t & 1;
        const float* an = act_b + nn * 64;
        float dotj[32];
#pragma unroll
        for (int j = 0; j < 32; j++) dotj[j] = 0.f;
        for (int al = 0; al < 64; al++) {
            float av = __ldg(&an[al]);
            const float4* g4 = (const float4*)&g_G2[al * 64 + seg * 32];
#pragma unroll
            for (int q = 0; q < 8; q++) {
                float4 g = g4[q];
                dotj[q * 4 + 0] += av * g.x;
                dotj[q * 4 + 1] += av * g.y;
                dotj[q * 4 + 2] += av * g.z;
                dotj[q * 4 + 3] += av * g.w;
            }
        }
        float quad = 0.f, wbp = 0.f, wsp = 0.f;
#pragma unroll
        for (int j = 0; j < 32; j++) {
            int be = seg * 32 + j;
            float ab = __ldg(&an[be]);
            quad += ab * dotj[j];
            wbp += ab * g_wb[be];
            wsp += ab * g_wsum[be];
        }
        quad += __shfl_xor_sync(0xffffffffu, quad, 1);
        wbp  += __shfl_xor_sync(0xffffffffu, wbp, 1);
        wsp  += __shfl_xor_sync(0xffffffffu, wsp, 1);
        if (seg == 0) {
            float bb = g_scal[0], sb = g_scal[1];
            float mu = (wsp + sb) * (1.f / 512.f);
            float e2 = (quad + 2.f * wbp + bb) * (1.f / 512.f);
            float var = e2 - mu * mu;
            sMu[nn] = mu;
            sRs[nn] = rsqrtf(var + 1e-5f);
        }
    }
    __syncthreads();

    // ======== actRaug -> sActR [k][65] ========
    {
        const int nn = t >> 1, half = t & 1;
        const float* an = act_b + nn * 64;
        float rs = sRs[nn];
#pragma unroll
        for (int i = 0; i < 32; i++) {
            int al = half * 32 + i;
            sActR[al * 65 + nn] = rs * __ldg(&an[al]);
        }
        if (half == 0) {
            sActR[64 * 65 + nn] = rs;
            sActR[65 * 65 + nn] = -rs * sMu[nn];
            sActR[66 * 65 + nn] = 1.f;
        }
    }
    __syncthreads();

    // ======== Qe ========
    float* qdst_base = g_QeT + (size_t)b * 8704;
#pragma unroll
    for (int pass = 0; pass < 2; pass++) {
        int k = pass ? (64 + (t >> 1)) : (t >> 1);
        bool active = (pass == 0) || (t < 6);
        if (active) {
            const int shalf = t & 1;
            u64 qacc[16];
#pragma unroll
            for (int j = 0; j < 16; j++) qacc[j] = 0ull;
            float cs = 0.f;
            for (int nn = 0; nn < 64; nn++) {
                float a = sActR[k * 65 + nn];
                cs += a;
                u64 ad = dup2(a);
                const ulonglong2* ep =
                    (const ulonglong2*)&sAttn[nn * 68 + shalf * 32];
#pragma unroll
                for (int jj = 0; jj < 8; jj++) {
                    ulonglong2 e = ep[jj];
                    qacc[2 * jj]     = fma2(ad, e.x, qacc[2 * jj]);
                    qacc[2 * jj + 1] = fma2(ad, e.y, qacc[2 * jj + 1]);
                }
            }
            u64 ec = dup2(cs * 1e-8f);
            u64 one = dup2(1.f);
            float* dst = qdst_base + k * 128 + shalf * 64;
#pragma unroll
            for (int j = 0; j < 16; j++) {
                qacc[j] = fma2(ec, one, qacc[j]);
                float2 p = unpk(qacc[j]);
                *(float4*)(dst + 4 * j) = make_float4(p.x, p.x, p.y, p.y);
            }
        }
    }
}

// =================== kernel B: out = Qe @ M1e (R10/R14-measured version) =========
__global__ __launch_bounds__(256, 2)
void out_kernel(float* __restrict__ out_slots) {
    const int t = threadIdx.x;
    const int b = blockIdx.x;
    const int fy = blockIdx.y;
    const int w = t >> 5, l = t & 31;
    const int s0 = w * 8;
    const int f = fy * 256 + l * 8;
    const float* Qb = g_QeT + (size_t)b * 8704;

    u64 acc[8][4];
#pragma unroll
    for (int i = 0; i < 8; i++)
#pragma unroll
        for (int p = 0; p < 4; p++) acc[i][p] = 0ull;

#pragma unroll 4
    for (int k = 0; k < 67; k++) {
        const ulonglong2* m = (const ulonglong2*)&g_M1e[k * 512 + f];
        ulonglong2 m0 = m[0], m1 = m[1];
        const ulonglong2* q = (const ulonglong2*)&Qb[k * 128 + 2 * s0];
        ulonglong2 q0 = q[0], q1 = q[1], q2 = q[2], q3 = q[3];
        u64 e[8] = {q0.x, q0.y, q1.x, q1.y, q2.x, q2.y, q3.x, q3.y};
#pragma unroll
        for (int i = 0; i < 8; i++) {
            acc[i][0] = fma2(e[i], m0.x, acc[i][0]);
            acc[i][1] = fma2(e[i], m0.y, acc[i][1]);
            acc[i][2] = fma2(e[i], m1.x, acc[i][2]);
            acc[i][3] = fma2(e[i], m1.y, acc[i][3]);
        }
    }

    float* o1 = out_slots + (size_t)b * S_ * F_ + f;
#pragma unroll
    for (int i = 0; i < 8; i++) {
        float2 p0 = unpk(acc[i][0]), p1 = unpk(acc[i][1]);
        float2 p2 = unpk(acc[i][2]), p3 = unpk(acc[i][3]);
        float* dst = o1 + (s0 + i) * 512;
        *(float4*)dst       = make_float4(p0.x, p0.y, p1.x, p1.y);
        *(float4*)(dst + 4) = make_float4(p2.x, p2.y, p3.x, p3.y);
    }
}

// ---------------- launch ----------------------------------------------------------
extern "C" void kernel_launch(void* const* d_in, const int* in_sizes, int n_in,
                              void* d_out, int out_size) {
    const float* slots   = (const float*)d_in[0];
    const float* actions = (const float*)d_in[1];
    const float* W_ae    = (const float*)d_in[2];
    const float* b_ae    = (const float*)d_in[3];
    const float* W_ie    = (const float*)d_in[4];
    const float* b_ie    = (const float*)d_in[5];
    const float* ln_g    = (const float*)d_in[6];
    const float* ln_b    = (const float*)d_in[7];
    const float* Wq      = (const float*)d_in[8];
    const float* Wk      = (const float*)d_in[9];
    const float* Wv      = (const float*)d_in[10];

    float* out      = (float*)d_out;
    float* out_attn = out + (size_t)B_ * S_ * F_;

    setup_master<<<138, 512>>>(W_ae, b_ae, W_ie, b_ie, ln_g, ln_b, Wk, Wv);
    setup_kq<<<dim3(8, 8), 64>>>(Wq);

    const size_t AQ_BYTES = AQ_FLOATS * sizeof(float);
    cudaFuncSetAttribute(attnq_kernel,
                         cudaFuncAttributeMaxDynamicSharedMemorySize, (int)AQ_BYTES);
    attnq_kernel<<<B_, 128, AQ_BYTES>>>(slots, actions, out_attn);

    out_kernel<<<dim3(B_, 2), 256>>>(out);
}

// round 17
// speedup vs baseline: 1.1715x; 1.0185x over previous
#include <cuda_runtime.h>
#include <cstdint>

#define B_ 2048
#define S_ 64
#define D_ 512
#define N_ 64
#define A_ 64
#define F_ 512

typedef unsigned long long u64;

// ---------------- persistent device scratch ------------------------------------
__device__ __align__(16) float g_k[N_ * F_];
__device__ __align__(16) float g_kqP[(size_t)D_ * N_];     // plain [d][n], scale folded
__device__ __align__(16) float g_M1e[68 * F_];
__device__ __align__(16) float g_G2[A_ * A_];
__device__ __align__(16) float g_wb[A_];
__device__ __align__(16) float g_wsum[A_];
__device__ __align__(16) float g_scal[2];
__device__ __align__(16) float g_QeT[(size_t)B_ * 68 * 128];  // dup pairs [b][k][2s]

// ---------------- f32x2 / async helpers -------------------------------------------
__device__ __forceinline__ u64 fma2(u64 a, u64 b, u64 c) {
    u64 d;
    asm("fma.rn.f32x2 %0, %1, %2, %3;" : "=l"(d) : "l"(a), "l"(b), "l"(c));
    return d;
}
__device__ __forceinline__ u64 dup2(float v) {
    u64 d;
    asm("mov.b64 %0, {%1, %1};" : "=l"(d) : "f"(v));
    return d;
}
__device__ __forceinline__ u64 pk2(float a, float b) {
    u64 d;
    asm("mov.b64 %0, {%1, %2};" : "=l"(d) : "f"(a), "f"(b));
    return d;
}
__device__ __forceinline__ float2 unpk(u64 v) {
    float2 r;
    asm("mov.b64 {%0, %1}, %2;" : "=f"(r.x), "=f"(r.y) : "l"(v));
    return r;
}
__device__ __forceinline__ uint32_t smem_u32(const void* p) {
    uint32_t a;
    asm("{ .reg .u64 t; cvta.to.shared.u64 t, %1; cvt.u32.u64 %0, t; }"
        : "=r"(a) : "l"(p));
    return a;
}
__device__ __forceinline__ void cp16(uint32_t dst, const void* src) {
    asm volatile("cp.async.ca.shared.global [%0], [%1], 16;"
                 :: "r"(dst), "l"(src) : "memory");
}
#define CP_COMMIT() asm volatile("cp.async.commit_group;" ::: "memory")
#define CP_WAIT0()  asm volatile("cp.async.wait_group 0;" ::: "memory")

// ---------------- setup: M1e, G2, scalars, k -------------------------------------
__global__ __launch_bounds__(512)
void setup_master(const float* __restrict__ W_ae, const float* __restrict__ b_ae,
                  const float* __restrict__ W_ie, const float* __restrict__ b_ie,
                  const float* __restrict__ ln_g, const float* __restrict__ ln_b,
                  const float* __restrict__ Wk, const float* __restrict__ Wv) {
    const int t = threadIdx.x;
    const int b = blockIdx.x;
    if (b < 64) {
        float a0 = 0.f, a1 = 0.f, a2 = 0.f, a3 = 0.f;
        for (int f = 0; f < F_; f += 4) {
            float4 wv = *(const float4*)&Wv[t * 512 + f];
            float4 lg = *(const float4*)&ln_g[f];
            a0 += W_ae[(f + 0) * A_ + b] * lg.x * wv.x;
            a1 += W_ae[(f + 1) * A_ + b] * lg.y * wv.y;
            a2 += W_ae[(f + 2) * A_ + b] * lg.z * wv.z;
            a3 += W_ae[(f + 3) * A_ + b] * lg.w * wv.w;
        }
        g_M1e[b * 512 + t] = (a0 + a1) + (a2 + a3);
    } else if (b == 64) {
        float c1 = 0.f, c2 = 0.f, c3 = 0.f;
        for (int f = 0; f < F_; f += 2) {
            float2 wv = *(const float2*)&Wv[t * 512 + f];
            c1 += b_ae[f] * ln_g[f] * wv.x + b_ae[f + 1] * ln_g[f + 1] * wv.y;
            c2 += ln_g[f] * wv.x + ln_g[f + 1] * wv.y;
            c3 += ln_b[f] * wv.x + ln_b[f + 1] * wv.y;
        }
        g_M1e[64 * 512 + t] = c1;
        g_M1e[65 * 512 + t] = c2;
        g_M1e[66 * 512 + t] = c3;
        g_M1e[67 * 512 + t] = 0.f;
    } else if (b < 73) {
        int idx = (b - 65) * 512 + t;
        int al = idx & 63, be = idx >> 6;
        float a0 = 0.f, a1 = 0.f, a2 = 0.f, a3 = 0.f;
#pragma unroll 4
        for (int f = 0; f < F_; f += 4) {
            a0 += W_ae[(f + 0) * A_ + al] * W_ae[(f + 0) * A_ + be];
            a1 += W_ae[(f + 1) * A_ + al] * W_ae[(f + 1) * A_ + be];
            a2 += W_ae[(f + 2) * A_ + al] * W_ae[(f + 2) * A_ + be];
            a3 += W_ae[(f + 3) * A_ + al] * W_ae[(f + 3) * A_ + be];
        }
        g_G2[al * A_ + be] = (a0 + a1) + (a2 + a3);
    } else if (b == 73) {
        if (t < 64) {
            float aw = 0.f, as = 0.f;
#pragma unroll 4
            for (int f = 0; f < F_; f++) {
                float w = W_ae[f * A_ + t];
                aw += w * b_ae[f];
                as += w;
            }
            g_wb[t] = aw;
            g_wsum[t] = as;
        } else if (t == 64) {
            float bb = 0.f, sb = 0.f;
            for (int f = 0; f < F_; f++) {
                float v = b_ae[f];
                bb += v * v;
                sb += v;
            }
            g_scal[0] = bb;
            g_scal[1] = sb;
        }
    } else {
        int idx = (b - 74) * 512 + t;
        int n = idx & 63;
        int g = idx >> 6;
        float a0 = 0.f, a1 = 0.f, a2 = 0.f, a3 = 0.f;
#pragma unroll 4
        for (int f = 0; f < F_; f += 4) {
            a0 += (W_ie[(f + 0) * N_ + n] + b_ie[f + 0]) * Wk[g * F_ + f + 0];
            a1 += (W_ie[(f + 1) * N_ + n] + b_ie[f + 1]) * Wk[g * F_ + f + 1];
            a2 += (W_ie[(f + 2) * N_ + n] + b_ie[f + 2]) * Wk[g * F_ + f + 2];
            a3 += (W_ie[(f + 3) * N_ + n] + b_ie[f + 3]) * Wk[g * F_ + f + 3];
        }
        g_k[n * F_ + g] = (a0 + a1) + (a2 + a3);
    }
}

// ---------------- setup 2: kqP plain (single launch, grid 8x8) --------------------
__global__ void setup_kq(const float* __restrict__ Wq) {
    int d = blockIdx.y * 64 + threadIdx.x;
    int n0 = blockIdx.x * 8;
    float acc[8];
#pragma unroll
    for (int j = 0; j < 8; j++) acc[j] = 0.f;
#pragma unroll 4
    for (int f = 0; f < F_; f++) {
        float wq = Wq[f * D_ + d];
#pragma unroll
        for (int j = 0; j < 8; j++)
            acc[j] += g_k[(n0 + j) * F_ + f] * wq;
    }
    const float scale = 0.04419417382415922f;  // 512^-0.5
#pragma unroll
    for (int j = 0; j < 8; j++)
        g_kqP[(size_t)d * 64 + n0 + j] = acc[j] * scale;
}

// =================== kernel A v6.1: broadcast-economy + cp.async kq ===============
#define AQ_R1     0
#define AQ_R2     4356
#define AQ_RED    (4356 + 4352)
#define AQ_FLOATS (AQ_RED + 128)
__global__ __launch_bounds__(128, 5)
void attnq_kernel(const float* __restrict__ slots,
                  const float* __restrict__ actions,
                  float* __restrict__ out_attn) {
    extern __shared__ float sq[];
    float* sSlT  = sq + AQ_R1;     // [d][64] XOR-16B swizzled
    float* sActR = sq + AQ_R1;     // [k][65] after phase L
    float* sKq   = sq + AQ_R2;     // [d][64] plain
    float* sAttn = sq + AQ_R2;     // [n][68] after phase L
    float* sRed  = sq + AQ_RED;    // 128 (softmax exchange)
    float* sMu   = sq + AQ_RED;    // 64 (stats, after softmax)
    float* sRs   = sMu + 64;       // 64

    const int t = threadIdx.x;
    const int b = blockIdx.x;
    const float* slots_b = slots + (size_t)b * S_ * D_;
    const float* act_b   = actions + (size_t)b * N_ * A_;
    const int w = t >> 5, l = t & 31;
    const int nh = w >> 1, sh = w & 1;
    const int n = nh * 32 + l;
    const uint32_t sKqAddr = smem_u32(sKq);

    // ======== Phase L ========
    u64 acc[16];
#pragma unroll
    for (int j = 0; j < 16; j++) acc[j] = 0ull;

    for (int dc = 0; dc < 8; dc++) {
        if (dc) __syncthreads();
#pragma unroll
        for (int j = 0; j < 8; j++) {
            int idx = t + j * 128;            // 1024 16B units
            cp16(sKqAddr + idx * 16, &g_kqP[(size_t)dc * 4096 + idx * 4]);
        }
        CP_COMMIT();
#pragma unroll
        for (int j = 0; j < 8; j++) {
            int idx = t + j * 128;
            int s = idx >> 4, q = idx & 15;
            float4 v = *(const float4*)&slots_b[s * 512 + dc * 64 + q * 4];
            int c = s >> 2, slo = s & 3;
            float vv[4] = {v.x, v.y, v.z, v.w};
#pragma unroll
            for (int k = 0; k < 4; k++) {
                int d = q * 4 + k;
                sSlT[d * 64 + ((c ^ (d & 15)) << 2) + slo] = vv[k];
            }
        }
        CP_WAIT0();
        __syncthreads();

#pragma unroll 4
        for (int d = 0; d < 64; d++) {
            u64 kd = dup2(sKq[d * 64 + nh * 32 + l]);   // lane-contig, 1 wf
            int dx = d & 15;
            const float* row = &sSlT[d * 64];
#pragma unroll
            for (int cc = 0; cc < 8; cc += 2) {
                int c0 = sh * 8 + cc;
                ulonglong2 v0 = *(const ulonglong2*)&row[((c0 ^ dx) << 2)];
                ulonglong2 v1 = *(const ulonglong2*)&row[(((c0 + 1) ^ dx) << 2)];
                acc[2 * cc + 0] = fma2(kd, v0.x, acc[2 * cc + 0]);
                acc[2 * cc + 1] = fma2(kd, v0.y, acc[2 * cc + 1]);
                acc[2 * cc + 2] = fma2(kd, v1.x, acc[2 * cc + 2]);
                acc[2 * cc + 3] = fma2(kd, v1.y, acc[2 * cc + 3]);
            }
        }
    }
    __syncthreads();

    // ======== softmax over s ========
    {
        float lv[32];
#pragma unroll
        for (int j = 0; j < 16; j++) {
            float2 p = unpk(acc[j]);
            lv[2 * j] = p.x;
            lv[2 * j + 1] = p.y;
        }
        float pm = lv[0];
#pragma unroll
        for (int j = 1; j < 32; j++) pm = fmaxf(pm, lv[j]);
        sRed[sh * 64 + n] = pm;
        __syncthreads();
        float M = fmaxf(sRed[n], sRed[64 + n]);
        float ps = 0.f;
#pragma unroll
        for (int j = 0; j < 32; j++) {
            lv[j] = __expf(lv[j] - M);
            ps += lv[j];
        }
        __syncthreads();
        sRed[sh * 64 + n] = ps;
        __syncthreads();
        float inv = 1.f / (sRed[n] + sRed[64 + n]);
#pragma unroll
        for (int j = 0; j < 16; j++) {
            float e0 = lv[2 * j] * inv, e1 = lv[2 * j + 1] * inv;
            *(u64*)&sAttn[n * 68 + sh * 32 + 2 * j] = pk2(e0, e1);
        }
    }
    __syncthreads();

    // ======== write out_attn coalesced ========
    {
        float* o2 = out_attn + (size_t)b * N_ * S_;
#pragma unroll
        for (int j = 0; j < 8; j++) {
            int i4 = t + j * 128;
            int nn = i4 >> 4, sqd = i4 & 15;
            *(float4*)&o2[nn * 64 + sqd * 4] =
                *(const float4*)&sAttn[nn * 68 + sqd * 4];
        }
    }
    __syncthreads();

    // ======== LN stats: n = t>>1, seg = t&1; actions via __ldg ========
    {
        const int nn = t >> 1, seg = t & 1;
        const float* an = act_b + nn * 64;
        float dotj[32];
#pragma unroll
        for (int j = 0; j < 32; j++) dotj[j] = 0.f;
        for (int al = 0; al < 64; al++) {
            float av = __ldg(&an[al]);
            const float4* g4 = (const float4*)&g_G2[al * 64 + seg * 32];
#pragma unroll
            for (int q = 0; q < 8; q++) {
                float4 g = g4[q];
                dotj[q * 4 + 0] += av * g.x;
                dotj[q * 4 + 1] += av * g.y;
                dotj[q * 4 + 2] += av * g.z;
                dotj[q * 4 + 3] += av * g.w;
            }
        }
        float quad = 0.f, wbp = 0.f, wsp = 0.f;
#pragma unroll
        for (int j = 0; j < 32; j++) {
            int be = seg * 32 + j;
            float ab = __ldg(&an[be]);
            quad += ab * dotj[j];
            wbp += ab * g_wb[be];
            wsp += ab * g_wsum[be];
        }
        quad += __shfl_xor_sync(0xffffffffu, quad, 1);
        wbp  += __shfl_xor_sync(0xffffffffu, wbp, 1);
        wsp  += __shfl_xor_sync(0xffffffffu, wsp, 1);
        if (seg == 0) {
            float bb = g_scal[0], sb = g_scal[1];
            float mu = (wsp + sb) * (1.f / 512.f);
            float e2 = (quad + 2.f * wbp + bb) * (1.f / 512.f);
            float var = e2 - mu * mu;
            sMu[nn] = mu;
            sRs[nn] = rsqrtf(var + 1e-5f);
        }
    }
    __syncthreads();

    // ======== actRaug -> sActR [k][65] ========
    {
        const int nn = t >> 1, half = t & 1;
        const float* an = act_b + nn * 64;
        float rs = sRs[nn];
#pragma unroll
        for (int i = 0; i < 32; i++) {
            int al = half * 32 + i;
            sActR[al * 65 + nn] = rs * __ldg(&an[al]);
        }
        if (half == 0) {
            sActR[64 * 65 + nn] = rs;
            sActR[65 * 65 + nn] = -rs * sMu[nn];
            sActR[66 * 65 + nn] = 1.f;
        }
    }
    __syncthreads();

    // ======== Qe ========
    float* qdst_base = g_QeT + (size_t)b * 8704;
#pragma unroll
    for (int pass = 0; pass < 2; pass++) {
        int k = pass ? (64 + (t >> 1)) : (t >> 1);
        bool active = (pass == 0) || (t < 6);
        if (active) {
            const int shalf = t & 1;
            u64 qacc[16];
#pragma unroll
            for (int j = 0; j < 16; j++) qacc[j] = 0ull;
            float cs = 0.f;
            for (int nn = 0; nn < 64; nn++) {
                float a = sActR[k * 65 + nn];
                cs += a;
                u64 ad = dup2(a);
                const ulonglong2* ep =
                    (const ulonglong2*)&sAttn[nn * 68 + shalf * 32];
#pragma unroll
                for (int jj = 0; jj < 8; jj++) {
                    ulonglong2 e = ep[jj];
                    qacc[2 * jj]     = fma2(ad, e.x, qacc[2 * jj]);
                    qacc[2 * jj + 1] = fma2(ad, e.y, qacc[2 * jj + 1]);
                }
            }
            u64 ec = dup2(cs * 1e-8f);
            u64 one = dup2(1.f);
            float* dst = qdst_base + k * 128 + shalf * 64;
#pragma unroll
            for (int j = 0; j < 16; j++) {
                qacc[j] = fma2(ec, one, qacc[j]);
                float2 p = unpk(qacc[j]);
                *(float4*)(dst + 4 * j) = make_float4(p.x, p.x, p.y, p.y);
            }
        }
    }
}

// =================== kernel B: out = Qe @ M1e (dense-f, isolated test) ===========
// grid (2048, 2), 256 threads. warp w -> s0 = 8w; lane l -> fa = fy*256+l*4, fb=+128.
__global__ __launch_bounds__(256, 2)
void out_kernel(float* __restrict__ out_slots) {
    const int t = threadIdx.x;
    const int b = blockIdx.x;
    const int fy = blockIdx.y;
    const int w = t >> 5, l = t & 31;
    const int s0 = w * 8;
    const int fa = fy * 256 + l * 4;
    const int fb = fa + 128;
    const float* Qb = g_QeT + (size_t)b * 8704;

    u64 acc[8][4];
#pragma unroll
    for (int i = 0; i < 8; i++)
#pragma unroll
        for (int p = 0; p < 4; p++) acc[i][p] = 0ull;

#pragma unroll 4
    for (int k = 0; k < 67; k++) {
        ulonglong2 ma = *(const ulonglong2*)&g_M1e[k * 512 + fa];  // 4-line dense
        ulonglong2 mb = *(const ulonglong2*)&g_M1e[k * 512 + fb];  // 4-line dense
        const ulonglong2* q = (const ulonglong2*)&Qb[k * 128 + 2 * s0];
        ulonglong2 q0 = q[0], q1 = q[1], q2 = q[2], q3 = q[3];
        u64 e[8] = {q0.x, q0.y, q1.x, q1.y, q2.x, q2.y, q3.x, q3.y};
#pragma unroll
        for (int i = 0; i < 8; i++) {
            acc[i][0] = fma2(e[i], ma.x, acc[i][0]);
            acc[i][1] = fma2(e[i], ma.y, acc[i][1]);
            acc[i][2] = fma2(e[i], mb.x, acc[i][2]);
            acc[i][3] = fma2(e[i], mb.y, acc[i][3]);
        }
    }

    float* o1 = out_slots + (size_t)b * S_ * F_;
#pragma unroll
    for (int i = 0; i < 8; i++) {
        float2 p0 = unpk(acc[i][0]), p1 = unpk(acc[i][1]);
        float2 p2 = unpk(acc[i][2]), p3 = unpk(acc[i][3]);
        float* dst = o1 + (s0 + i) * 512;
        *(float4*)(dst + fa) = make_float4(p0.x, p0.y, p1.x, p1.y);
        *(float4*)(dst + fb) = make_float4(p2.x, p2.y, p3.x, p3.y);
    }
}

// ---------------- launch ----------------------------------------------------------
extern "C" void kernel_launch(void* const* d_in, const int* in_sizes, int n_in,
                              void* d_out, int out_size) {
    const float* slots   = (const float*)d_in[0];
    const float* actions = (const float*)d_in[1];
    const float* W_ae    = (const float*)d_in[2];
    const float* b_ae    = (const float*)d_in[3];
    const float* W_ie    = (const float*)d_in[4];
    const float* b_ie    = (const float*)d_in[5];
    const float* ln_g    = (const float*)d_in[6];
    const float* ln_b    = (const float*)d_in[7];
    const float* Wq      = (const float*)d_in[8];
    const float* Wk      = (const float*)d_in[9];
    const float* Wv      = (const float*)d_in[10];

    float* out      = (float*)d_out;
    float* out_attn = out + (size_t)B_ * S_ * F_;

    setup_master<<<138, 512>>>(W_ae, b_ae, W_ie, b_ie, ln_g, ln_b, Wk, Wv);
    setup_kq<<<dim3(8, 8), 64>>>(Wq);

    const size_t AQ_BYTES = AQ_FLOATS * sizeof(float);
    cudaFuncSetAttribute(attnq_kernel,
                         cudaFuncAttributeMaxDynamicSharedMemorySize, (int)AQ_BYTES);
    attnq_kernel<<<B_, 128, AQ_BYTES>>>(slots, actions, out_attn);

    out_kernel<<<dim3(B_, 2), 256>>>(out);   // 4th launch -> profiled
}